// round 17
// baseline (speedup 1.0000x reference)
#include <cuda_runtime.h>

// Problem constants (B=1, N=4, C=16, D=64, H=128, W=128)
#define NCTX 4
#define CH   16
#define VOX  (64 * 128 * 128)   // 1,048,576 voxels
#define VPT  2                  // voxels per thread (float2)
#define TPB  128                // smaller CTAs: 8 independent CTAs/SM
#define NSM  148
#define CTAS_PER_SM 8
#define GRID (NSM * CTAS_PER_SM)            // 1184 persistent CTAs
#define NTILES (VOX / (TPB * VPT))          // 4096 tiles

__device__ __forceinline__ float frcp_approx(float x) {
    float r;
    asm("rcp.approx.f32 %0, %1;" : "=f"(r) : "f"(x));
    return r;
}

__global__ __launch_bounds__(TPB, CTAS_PER_SM) void volattn3d_kernel(
    const float* __restrict__ q,      // [C][V]
    const float* __restrict__ k,      // [N][C][V]
    const float* __restrict__ v,      // [N][C][V]
    const float* __restrict__ w_proj, // [C][C]
    const float* __restrict__ b_proj, // [C]
    float* __restrict__ out)          // [C][V]
{
    __shared__ float sw[CH * CH];
    __shared__ float sb[CH];
    {
        int t = threadIdx.x;
        // TPB=128: two rounds to fill the 256-entry weight tile
        sw[t]       = w_proj[t];
        sw[t + 128] = w_proj[t + 128];
        if (t < CH) sb[t] = b_proj[t];
    }
    __syncthreads();

    const int tid = threadIdx.x;

#pragma unroll 1
    for (int tile = blockIdx.x; tile < NTILES; tile += GRID) {
        const int p = (tile * TPB + tid) * VPT;   // base voxel pair
        const float* qp = q + p;
        const float* kp = k + p;
        const float* vp = v + p;

        // ---- phase A: scores[n] = (q . k_n) ----
        float2 sc[NCTX];
#pragma unroll
        for (int n = 0; n < NCTX; ++n) sc[n] = make_float2(0.f, 0.f);

#pragma unroll
        for (int c = 0; c < CH; ++c) {
            const float2 qv = __ldcs(reinterpret_cast<const float2*>(qp + c * VOX));
#pragma unroll
            for (int n = 0; n < NCTX; ++n) {
                const float2 kv = __ldcs(reinterpret_cast<const float2*>(kp + (n * CH + c) * VOX));
                sc[n].x = fmaf(qv.x, kv.x, sc[n].x);
                sc[n].y = fmaf(qv.y, kv.y, sc[n].y);
            }
        }

        // ---- unnormalized softmax weights: e_n = exp(s_n / 4) ----
        // scores ~N(0,1): fp32 exp needs no max-subtraction; normalization
        // is deferred to the epilogue so phase B is gated only by each exp.
        float2 ssum = make_float2(0.f, 0.f);
#pragma unroll
        for (int n = 0; n < NCTX; ++n) {
            sc[n].x = __expf(sc[n].x * 0.25f);
            sc[n].y = __expf(sc[n].y * 0.25f);
            ssum.x += sc[n].x;
            ssum.y += sc[n].y;
        }
        const float2 rs = make_float2(frcp_approx(ssum.x), frcp_approx(ssum.y));

        // ---- phase B: x~[c] = sum_n e_n * v[n][c]  (unnormalized) ----
        float2 x[CH];
#pragma unroll
        for (int c = 0; c < CH; ++c) x[c] = make_float2(0.f, 0.f);
#pragma unroll
        for (int n = 0; n < NCTX; ++n) {
#pragma unroll
            for (int c = 0; c < CH; ++c) {
                const float2 vv = __ldcs(reinterpret_cast<const float2*>(vp + (n * CH + c) * VOX));
                x[c].x = fmaf(sc[n].x, vv.x, x[c].x);
                x[c].y = fmaf(sc[n].y, vv.y, x[c].y);
            }
        }

        // ---- phase C: out[o] = (sum_c w[o][c] * x~[c]) * rs + b[o] ----
        float* op = out + p;
#pragma unroll
        for (int o = 0; o < CH; ++o) {
            float2 acc = make_float2(0.f, 0.f);
#pragma unroll
            for (int c = 0; c < CH; ++c) {
                const float wv = sw[o * CH + c];
                acc.x = fmaf(wv, x[c].x, acc.x);
                acc.y = fmaf(wv, x[c].y, acc.y);
            }
            const float bo = sb[o];
            acc.x = fmaf(acc.x, rs.x, bo);
            acc.y = fmaf(acc.y, rs.y, bo);
            __stcs(reinterpret_cast<float2*>(op + o * VOX), acc);
        }
    }
}

extern "C" void kernel_launch(void* const* d_in, const int* in_sizes, int n_in,
                              void* d_out, int out_size) {
    const float* q      = (const float*)d_in[0];
    const float* k      = (const float*)d_in[1];
    const float* v      = (const float*)d_in[2];
    const float* w_proj = (const float*)d_in[3];
    const float* b_proj = (const float*)d_in[4];
    float* out = (float*)d_out;

    volattn3d_kernel<<<GRID, TPB>>>(q, k, v, w_proj, b_proj, out);
}